// round 6
// baseline (speedup 1.0000x reference)
#include <cuda_runtime.h>
#include <cstdint>

#define N_NODES 50000
#define X_DIMS 256
#define Y_DIMS 64

// ---------------- scratch (no cudaMalloc allowed) ----------------
__device__ int   g_row_ptr[N_NODES + 1];
__device__ float g_x1[(size_t)N_NODES * X_DIMS];
__device__ float g_x2[(size_t)N_NODES * X_DIMS];
__device__ float g_y1[(size_t)N_NODES * Y_DIMS];
__device__ float g_y2[(size_t)N_NODES * Y_DIMS];
__device__ float g_sqn_x [N_NODES];
__device__ float g_sqn_y [N_NODES];
__device__ float g_sqn_x1[N_NODES];
__device__ float g_sqn_y1[N_NODES];

// ---------------- CSR row_ptr from sorted COO row ----------------
__global__ void build_rowptr_kernel(const int* __restrict__ row, int E, int n)
{
    int r = blockIdx.x * blockDim.x + threadIdx.x;
    if (r > n) return;
    int lo = 0, hi = E;
    while (lo < hi) {
        int mid = (lo + hi) >> 1;
        if (row[mid] < r) lo = mid + 1; else hi = mid;
    }
    g_row_ptr[r] = lo;
}

// ---------------- row load/store helpers ----------------
__device__ __forceinline__ void load_row(const float* __restrict__ p, int lane, float (&v)[8])
{
    float4 a = *(const float4*)(p + lane * 4);
    float4 b = *(const float4*)(p + 128 + lane * 4);
    v[0]=a.x; v[1]=a.y; v[2]=a.z; v[3]=a.w;
    v[4]=b.x; v[5]=b.y; v[6]=b.z; v[7]=b.w;
}
__device__ __forceinline__ void load_row(const float* __restrict__ p, int lane, float (&v)[2])
{
    float2 a = *(const float2*)(p + lane * 2);
    v[0]=a.x; v[1]=a.y;
}

// ---------------- squared-norm kernel (warp per row) ----------------
template <int D>
__global__ void __launch_bounds__(256) norm_kernel(
    const float* __restrict__ feats, float* __restrict__ sqn, int n)
{
    constexpr int C = D / 32;
    int gw   = (int)((blockIdx.x * 256u + threadIdx.x) >> 5);
    int lane = threadIdx.x & 31;
    if (gw >= n) return;
    float fr[C];
    load_row(feats + (size_t)gw * D, lane, fr);
    float s = 0.0f;
#pragma unroll
    for (int i = 0; i < C; i++) s = fmaf(fr[i], fr[i], s);
#pragma unroll
    for (int o = 16; o > 0; o >>= 1)
        s += __shfl_xor_sync(0xffffffffu, s, o);
    if (lane == 0) sqn[gw] = s;
}

// ---------------- prop: TWO warps per row, U edge-chains per warp ----------
// Warp parity splits the edge list (stride 2); partials combined in smem.
// ||fr-fc||^2 = nr + nc - 2 dot(fr,fc); per-node sq-norms precomputed.
template <int D, int U, bool WN>
__global__ void __launch_bounds__(256) prop_kernel(
    const float* __restrict__ feats,
    const int*   __restrict__ col,
    const float* __restrict__ sqn_src,
    float*       __restrict__ sqn_dst,
    const float* __restrict__ sigmas, int sidx,
    float* __restrict__ out, int n)
{
    constexpr int C = D / 32;
    __shared__ float sacc[4][D];
    __shared__ float sden[4];

    int tid  = threadIdx.x;
    int lane = tid & 31;
    int warp = tid >> 5;
    int rs   = warp >> 1;            // row slot 0..3
    int half = warp & 1;             // edge-parity owned by this warp
    int gw   = blockIdx.x * 4 + rs;
    bool valid = gw < n;

    float fr[C], acc[C];
    float den = 0.0f, inv_s2 = 0.0f, t2 = 0.0f, bnr = 0.0f;
#pragma unroll
    for (int i = 0; i < C; i++) acc[i] = 0.0f;

    if (valid) {
        float sg = sigmas[sidx];
        inv_s2 = 1.0f / (sg * sg);
        t2 = 2.0f * inv_s2;

        int e0 = g_row_ptr[gw];
        int e1 = g_row_ptr[gw + 1];

        load_row(feats + (size_t)gw * D, lane, fr);
        bnr = -sqn_src[gw] * inv_s2;

        int e = e0 + half;
        for (; e + 2 * (U - 1) < e1; e += 2 * U) {
            int cs[U];
            float nc[U];
#pragma unroll
            for (int j = 0; j < U; j++) {
                cs[j] = __ldg(col + e + 2 * j);
                nc[j] = __ldg(sqn_src + cs[j]);
            }
            float fc[U][C];
#pragma unroll
            for (int j = 0; j < U; j++)
                load_row(feats + (size_t)cs[j] * D, lane, fc[j]);

            float dt[U];
#pragma unroll
            for (int j = 0; j < U; j++) {
                float d = 0.0f;
#pragma unroll
                for (int i = 0; i < C; i++) d = fmaf(fr[i], fc[j][i], d);
                dt[j] = d;
            }
#pragma unroll
            for (int o = 16; o > 0; o >>= 1) {
#pragma unroll
                for (int j = 0; j < U; j++)
                    dt[j] += __shfl_xor_sync(0xffffffffu, dt[j], o);
            }
#pragma unroll
            for (int j = 0; j < U; j++) {
                float val = __expf(fmaf(t2, dt[j], fmaf(-inv_s2, nc[j], bnr)));
                den += val;
#pragma unroll
                for (int i = 0; i < C; i++) acc[i] = fmaf(val, fc[j][i], acc[i]);
            }
        }
        for (; e < e1; e += 2) {
            int c = __ldg(col + e);
            float ncv = __ldg(sqn_src + c);
            float fc[C];
            load_row(feats + (size_t)c * D, lane, fc);
            float d = 0.0f;
#pragma unroll
            for (int i = 0; i < C; i++) d = fmaf(fr[i], fc[i], d);
#pragma unroll
            for (int o = 16; o > 0; o >>= 1)
                d += __shfl_xor_sync(0xffffffffu, d, o);
            float val = __expf(fmaf(t2, d, fmaf(-inv_s2, ncv, bnr)));
            den += val;
#pragma unroll
            for (int i = 0; i < C; i++) acc[i] = fmaf(val, fc[i], acc[i]);
        }
    }

    // warp 1 publishes partials; warp 0 combines, normalizes, stores
    if (valid && half == 1) {
#pragma unroll
        for (int i = 0; i < C; i++) sacc[rs][i * 32 + lane] = acc[i];
        if (lane == 0) sden[rs] = den;
    }
    __syncthreads();
    if (valid && half == 0) {
#pragma unroll
        for (int i = 0; i < C; i++) acc[i] += sacc[rs][i * 32 + lane];
        den += sden[rs];

        float inv = (den > 0.0f) ? (1.0f / den) : 0.0f;
#pragma unroll
        for (int i = 0; i < C; i++) acc[i] *= inv;

        float* op = out + (size_t)gw * D;
        if (C == 8) {
            *(float4*)(op + lane * 4)       = make_float4(acc[0], acc[1], acc[2], acc[3]);
            *(float4*)(op + 128 + lane * 4) = make_float4(acc[4], acc[5], acc[6], acc[7]);
        } else {
            *(float2*)(op + lane * 2) = make_float2(acc[0], acc[1]);
        }

        if (WN) {
            float s = 0.0f;
#pragma unroll
            for (int i = 0; i < C; i++) s = fmaf(acc[i], acc[i], s);
#pragma unroll
            for (int o = 16; o > 0; o >>= 1)
                s += __shfl_xor_sync(0xffffffffu, s, o);
            if (lane == 0) sqn_dst[gw] = s;
        }
    }
}

// ---------------- tf32 GEMM v2: [M,896] @ [896,64] -------------------------
#define BM 128
#define BN 64
#define BK 32
#define AP (BK + 4)
#define BP (BN + 8)
#define NT 28
#define SMEM_GEMM (2 * (BM * AP + BK * BP) * 4)

__device__ __forceinline__ uint32_t f2tf32(float f)
{
    uint32_t u;
    asm("cvt.rna.tf32.f32 %0, %1;" : "=r"(u) : "f"(f));
    return u;
}

__device__ __forceinline__ void mma_tf32(float (&c)[4], const uint32_t (&a)[4], const uint32_t (&b)[2])
{
    asm volatile(
        "mma.sync.aligned.m16n8k8.row.col.f32.tf32.tf32.f32 "
        "{%0,%1,%2,%3}, {%4,%5,%6,%7}, {%8,%9}, {%0,%1,%2,%3};\n"
        : "+f"(c[0]), "+f"(c[1]), "+f"(c[2]), "+f"(c[3])
        : "r"(a[0]), "r"(a[1]), "r"(a[2]), "r"(a[3]), "r"(b[0]), "r"(b[1]));
}

__device__ __forceinline__ const float* tile_base(
    int t, const float* x, const float* x1, const float* x2,
    const float* y1, const float* y2, int& width)
{
    if (t < 8)  { width = X_DIMS; return x  + (t << 5); }
    if (t < 16) { width = X_DIMS; return x1 + ((t - 8) << 5); }
    if (t < 24) { width = X_DIMS; return x2 + ((t - 16) << 5); }
    if (t < 26) { width = Y_DIMS; return y1 + ((t - 24) << 5); }
    width = Y_DIMS; return y2 + ((t - 26) << 5);
}

__global__ void __launch_bounds__(256) gemm_tf32_kernel(
    const float* __restrict__ x,
    const float* __restrict__ x1,
    const float* __restrict__ x2,
    const float* __restrict__ y1,
    const float* __restrict__ y2,
    const float* __restrict__ W,
    float* __restrict__ out, int M)
{
    extern __shared__ uint32_t dsm[];
    uint32_t (*As)[BM][AP] = (uint32_t (*)[BM][AP])dsm;
    uint32_t (*Bs)[BK][BP] = (uint32_t (*)[BK][BP])(dsm + 2 * BM * AP);

    int tid  = threadIdx.x;
    int lane = tid & 31;
    int wid  = tid >> 5;
    int wm = (wid >> 1) * 32;
    int wn = (wid & 1) * 32;
    int g  = lane >> 2;
    int tk = lane & 3;
    int row0 = blockIdx.x * BM;

    int ar = tid >> 3;
    int kg = (tid & 7) * 4;
    int bk_ = tid >> 4;
    int bj  = (tid & 15) * 4;

    float4 pa[4];
    float4 pb[2];

    float c[2][4][4];
#pragma unroll
    for (int mt = 0; mt < 2; mt++)
#pragma unroll
        for (int nt = 0; nt < 4; nt++)
#pragma unroll
            for (int q = 0; q < 4; q++) c[mt][nt][q] = 0.0f;

#define LDG_TILE(t)                                                        \
    do {                                                                   \
        int width_;                                                        \
        const float* base_ = tile_base((t), x, x1, x2, y1, y2, width_);    \
        _Pragma("unroll")                                                  \
        for (int i = 0; i < 4; i++) {                                      \
            int grow = row0 + ar + 32 * i;                                 \
            pa[i] = make_float4(0.f, 0.f, 0.f, 0.f);                       \
            if (grow < M)                                                  \
                pa[i] = *(const float4*)(base_ + (size_t)grow * width_ + kg);\
        }                                                                  \
        _Pragma("unroll")                                                  \
        for (int i = 0; i < 2; i++) {                                      \
            int k_ = bk_ + 16 * i;                                         \
            pb[i] = *(const float4*)(W + (size_t)((t) * BK + k_) * BN + bj);\
        }                                                                  \
    } while (0)

#define STS_TILE(buf)                                                      \
    do {                                                                   \
        _Pragma("unroll")                                                  \
        for (int i = 0; i < 4; i++) {                                      \
            int r_ = ar + 32 * i;                                          \
            As[buf][r_][kg + 0] = f2tf32(pa[i].x);                         \
            As[buf][r_][kg + 1] = f2tf32(pa[i].y);                         \
            As[buf][r_][kg + 2] = f2tf32(pa[i].z);                         \
            As[buf][r_][kg + 3] = f2tf32(pa[i].w);                         \
        }                                                                  \
        _Pragma("unroll")                                                  \
        for (int i = 0; i < 2; i++) {                                      \
            int k_ = bk_ + 16 * i;                                         \
            Bs[buf][k_][bj + 0] = f2tf32(pb[i].x);                         \
            Bs[buf][k_][bj + 1] = f2tf32(pb[i].y);                         \
            Bs[buf][k_][bj + 2] = f2tf32(pb[i].z);                         \
            Bs[buf][k_][bj + 3] = f2tf32(pb[i].w);                         \
        }                                                                  \
    } while (0)

    LDG_TILE(0);
    STS_TILE(0);
    __syncthreads();

    for (int t = 0; t < NT; t++) {
        if (t + 1 < NT) LDG_TILE(t + 1);

        int buf = t & 1;
#pragma unroll
        for (int kk = 0; kk < BK; kk += 8) {
            uint32_t a[2][4];
#pragma unroll
            for (int mt = 0; mt < 2; mt++) {
                int mrow = wm + mt * 16 + g;
                a[mt][0] = As[buf][mrow][kk + tk];
                a[mt][1] = As[buf][mrow + 8][kk + tk];
                a[mt][2] = As[buf][mrow][kk + tk + 4];
                a[mt][3] = As[buf][mrow + 8][kk + tk + 4];
            }
            uint32_t b[4][2];
#pragma unroll
            for (int nt = 0; nt < 4; nt++) {
                int ncol = wn + nt * 8 + g;
                b[nt][0] = Bs[buf][kk + tk][ncol];
                b[nt][1] = Bs[buf][kk + tk + 4][ncol];
            }
#pragma unroll
            for (int mt = 0; mt < 2; mt++)
#pragma unroll
                for (int nt = 0; nt < 4; nt++)
                    mma_tf32(c[mt][nt], a[mt], b[nt]);
        }

        if (t + 1 < NT) {
            STS_TILE((t + 1) & 1);
            __syncthreads();
        }
    }

#pragma unroll
    for (int mt = 0; mt < 2; mt++) {
#pragma unroll
        for (int nt = 0; nt < 4; nt++) {
            int r0 = row0 + wm + mt * 16 + g;
            int cc = wn + nt * 8 + 2 * tk;
            if (r0 < M)
                *(float2*)(out + (size_t)r0 * BN + cc) = make_float2(c[mt][nt][0], c[mt][nt][1]);
            if (r0 + 8 < M)
                *(float2*)(out + (size_t)(r0 + 8) * BN + cc) = make_float2(c[mt][nt][2], c[mt][nt][3]);
        }
    }
}

// ---------------- launch ----------------
extern "C" void kernel_launch(void* const* d_in, const int* in_sizes, int n_in,
                              void* d_out, int out_size)
{
    const float* x   = (const float*)d_in[0];
    const float* y   = (const float*)d_in[1];
    const float* W   = (const float*)d_in[2];
    const float* sig = (const float*)d_in[3];
    const int*   row = (const int*)  d_in[4];
    const int*   col = (const int*)  d_in[5];

    int N = in_sizes[0] / X_DIMS;
    int E = in_sizes[4];

    float *px1, *px2, *py1, *py2, *nx, *ny, *nx1, *ny1;
    cudaGetSymbolAddress((void**)&px1, g_x1);
    cudaGetSymbolAddress((void**)&px2, g_x2);
    cudaGetSymbolAddress((void**)&py1, g_y1);
    cudaGetSymbolAddress((void**)&py2, g_y2);
    cudaGetSymbolAddress((void**)&nx,  g_sqn_x);
    cudaGetSymbolAddress((void**)&ny,  g_sqn_y);
    cudaGetSymbolAddress((void**)&nx1, g_sqn_x1);
    cudaGetSymbolAddress((void**)&ny1, g_sqn_y1);

    cudaFuncSetAttribute(gemm_tf32_kernel,
                         cudaFuncAttributeMaxDynamicSharedMemorySize, SMEM_GEMM);

    build_rowptr_kernel<<<(N + 1 + 255) / 256, 256>>>(row, E, N);

    int nb = (N * 32 + 255) / 256;   // warp-per-row grids (norm kernels)
    norm_kernel<X_DIMS><<<nb, 256>>>(x, nx, N);
    norm_kernel<Y_DIMS><<<nb, 256>>>(y, ny, N);

    int pb = (N + 3) / 4;            // 4 rows per block, 2 warps per row
    prop_kernel<X_DIMS, 2, true ><<<pb, 256>>>(x,   col, nx,  nx1, sig, 0, px1, N);
    prop_kernel<Y_DIMS, 4, true ><<<pb, 256>>>(y,   col, ny,  ny1, sig, 2, py1, N);
    prop_kernel<X_DIMS, 2, false><<<pb, 256>>>(px1, col, nx1, nullptr, sig, 1, px2, N);
    prop_kernel<Y_DIMS, 4, false><<<pb, 256>>>(py1, col, ny1, nullptr, sig, 3, py2, N);

    gemm_tf32_kernel<<<(N + BM - 1) / BM, 256, SMEM_GEMM>>>(
        x, px1, px2, py1, py2, W, (float*)d_out, N);
}